// round 1
// baseline (speedup 1.0000x reference)
#include <cuda_runtime.h>
#include <cuda_bf16.h>
#include <cstdint>

// GlobalQuantizedLatent: per-element scalar quantization against a 16-entry
// codebook (linspace(-0.5, 0.5, 16)).
//
// Reference returns (x, quantized, z_hat, indices) -> flattened into d_out as
// 4 contiguous fp32 streams of length N (indices cast to float).
//
// Strategy: HBM-bound streaming kernel. Closed-form nearest-index candidate
// k0 = round((x+0.5)*15), then exact argmin tie-break over {k0-1, k0, k0+1}
// using the reference's own arithmetic (fabsf(x - v[k]), strict <, ascending
// index) -> bit-identical indices to jnp.argmin over all 16 values.

__device__ __forceinline__ int quantize_one(float x, const float* __restrict__ sv,
                                            float& q_out) {
    // closed-form candidate
    float s = __fmaf_rn(x, 15.0f, 7.5f);      // (x + 0.5) * 15
    int k0 = __float2int_rn(s);
    k0 = min(max(k0, 0), 15);
    int km = max(k0 - 1, 0);
    int kp = min(k0 + 1, 15);

    // exact first-min-wins argmin over {km, k0, kp} (matches jnp.argmin)
    float vkm = sv[km], vk0 = sv[k0], vkp = sv[kp];
    float dbest = fabsf(x - vkm);
    int   bi    = km;
    float qv    = vkm;

    float d1 = fabsf(x - vk0);
    if (d1 < dbest) { dbest = d1; bi = k0; qv = vk0; }

    float d2 = fabsf(x - vkp);
    if (d2 < dbest) { bi = kp; qv = vkp; }

    q_out = qv;
    return bi;
}

__global__ void __launch_bounds__(256)
gql_kernel(const float* __restrict__ x,
           const float* __restrict__ values,
           float* __restrict__ out,
           int n)
{
    __shared__ float sv[16];
    if (threadIdx.x < 16) sv[threadIdx.x] = values[threadIdx.x];
    __syncthreads();

    float* __restrict__ out_x   = out;
    float* __restrict__ out_q   = out + (size_t)n;
    float* __restrict__ out_zh  = out + 2 * (size_t)n;
    float* __restrict__ out_idx = out + 3 * (size_t)n;

    int i4 = blockIdx.x * blockDim.x + threadIdx.x;   // float4 index
    int base = i4 * 4;
    int n4 = n >> 2;

    if (i4 < n4) {
        const float4 xv = *reinterpret_cast<const float4*>(x + base);

        float q0, q1, q2, q3;
        int b0 = quantize_one(xv.x, sv, q0);
        int b1 = quantize_one(xv.y, sv, q1);
        int b2 = quantize_one(xv.z, sv, q2);
        int b3 = quantize_one(xv.w, sv, q3);

        // z_hat = x + (q - x), forced reference-order arithmetic
        float4 zh;
        zh.x = __fadd_rn(xv.x, __fsub_rn(q0, xv.x));
        zh.y = __fadd_rn(xv.y, __fsub_rn(q1, xv.y));
        zh.z = __fadd_rn(xv.z, __fsub_rn(q2, xv.z));
        zh.w = __fadd_rn(xv.w, __fsub_rn(q3, xv.w));

        float4 qv = make_float4(q0, q1, q2, q3);
        float4 iv = make_float4((float)b0, (float)b1, (float)b2, (float)b3);

        *reinterpret_cast<float4*>(out_x   + base) = xv;
        *reinterpret_cast<float4*>(out_q   + base) = qv;
        *reinterpret_cast<float4*>(out_zh  + base) = zh;
        *reinterpret_cast<float4*>(out_idx + base) = iv;
    }

    // tail (n not divisible by 4) — not hit for N=16M, kept for safety
    if (blockIdx.x == 0 && threadIdx.x < (n & 3)) {
        int i = (n4 << 2) + threadIdx.x;
        float xi = x[i];
        float q;
        int b = quantize_one(xi, sv, q);
        out_x[i]   = xi;
        out_q[i]   = q;
        out_zh[i]  = __fadd_rn(xi, __fsub_rn(q, xi));
        out_idx[i] = (float)b;
    }
}

extern "C" void kernel_launch(void* const* d_in, const int* in_sizes, int n_in,
                              void* d_out, int out_size) {
    const float* x      = (const float*)d_in[0];
    const float* values = (const float*)d_in[1];
    float* out = (float*)d_out;
    int n = in_sizes[0];

    int n4 = (n + 3) / 4;
    int threads = 256;
    int blocks = (n4 + threads - 1) / threads;
    gql_kernel<<<blocks, threads>>>(x, values, out, n);
}

// round 2
// speedup vs baseline: 1.0081x; 1.0081x over previous
#include <cuda_runtime.h>
#include <cuda_bf16.h>
#include <cstdint>

// GlobalQuantizedLatent: per-element scalar quantization vs 16-entry codebook.
// Output = 4 contiguous fp32 streams [x, quantized, z_hat, indices(float)].
//
// R2: HBM-bound streaming. Changes vs R1:
//  - 2 independent float4 chunks per thread (MLP 1 -> 2, halves index overhead)
//  - streaming cache hints: __ldcs on x, __stcs on all stores (evict-first,
//    stop polluting L2 with 256MB of dead write data)
//  - 512 threads/block, 8192 blocks

__device__ __forceinline__ int quantize_one(float x, const float* __restrict__ sv,
                                            float& q_out) {
    float s = __fmaf_rn(x, 15.0f, 7.5f);      // (x + 0.5) * 15
    int k0 = __float2int_rn(s);
    k0 = min(max(k0, 0), 15);
    int km = max(k0 - 1, 0);
    int kp = min(k0 + 1, 15);

    // first-min-wins argmin over {km,k0,kp} == jnp.argmin over all 16
    float vkm = sv[km], vk0 = sv[k0], vkp = sv[kp];
    float dbest = fabsf(x - vkm);
    int   bi    = km;
    float qv    = vkm;

    float d1 = fabsf(x - vk0);
    if (d1 < dbest) { dbest = d1; bi = k0; qv = vk0; }

    float d2 = fabsf(x - vkp);
    if (d2 < dbest) { bi = kp; qv = vkp; }

    q_out = qv;
    return bi;
}

__device__ __forceinline__ void process4(const float4 xv, const float* __restrict__ sv,
                                         float4& qv, float4& zh, float4& iv) {
    float q0, q1, q2, q3;
    int b0 = quantize_one(xv.x, sv, q0);
    int b1 = quantize_one(xv.y, sv, q1);
    int b2 = quantize_one(xv.z, sv, q2);
    int b3 = quantize_one(xv.w, sv, q3);

    zh.x = __fadd_rn(xv.x, __fsub_rn(q0, xv.x));
    zh.y = __fadd_rn(xv.y, __fsub_rn(q1, xv.y));
    zh.z = __fadd_rn(xv.z, __fsub_rn(q2, xv.z));
    zh.w = __fadd_rn(xv.w, __fsub_rn(q3, xv.w));

    qv = make_float4(q0, q1, q2, q3);
    iv = make_float4((float)b0, (float)b1, (float)b2, (float)b3);
}

__global__ void __launch_bounds__(512)
gql_kernel(const float* __restrict__ x,
           const float* __restrict__ values,
           float* __restrict__ out,
           int n)
{
    __shared__ float sv[16];
    if (threadIdx.x < 16) sv[threadIdx.x] = values[threadIdx.x];
    __syncthreads();

    float* __restrict__ out_x   = out;
    float* __restrict__ out_q   = out + (size_t)n;
    float* __restrict__ out_zh  = out + 2 * (size_t)n;
    float* __restrict__ out_idx = out + 3 * (size_t)n;

    const int n4 = n >> 2;
    // tile of 2*blockDim float4s per block
    int i4a = blockIdx.x * (blockDim.x * 2) + threadIdx.x;
    int i4b = i4a + blockDim.x;

    // issue both loads up front (MLP = 2)
    float4 xa, xb;
    bool va = (i4a < n4), vb = (i4b < n4);
    if (va) xa = __ldcs(reinterpret_cast<const float4*>(x) + i4a);
    if (vb) xb = __ldcs(reinterpret_cast<const float4*>(x) + i4b);

    if (va) {
        float4 qv, zh, iv;
        process4(xa, sv, qv, zh, iv);
        int base = i4a * 4;
        __stcs(reinterpret_cast<float4*>(out_x   + base), xa);
        __stcs(reinterpret_cast<float4*>(out_q   + base), qv);
        __stcs(reinterpret_cast<float4*>(out_zh  + base), zh);
        __stcs(reinterpret_cast<float4*>(out_idx + base), iv);
    }
    if (vb) {
        float4 qv, zh, iv;
        process4(xb, sv, qv, zh, iv);
        int base = i4b * 4;
        __stcs(reinterpret_cast<float4*>(out_x   + base), xb);
        __stcs(reinterpret_cast<float4*>(out_q   + base), qv);
        __stcs(reinterpret_cast<float4*>(out_zh  + base), zh);
        __stcs(reinterpret_cast<float4*>(out_idx + base), iv);
    }

    // scalar tail (n not divisible by 4) — not hit for N=16M
    if (blockIdx.x == 0 && threadIdx.x < (n & 3)) {
        int i = (n4 << 2) + threadIdx.x;
        float xi = x[i];
        float q;
        int b = quantize_one(xi, sv, q);
        out_x[i]   = xi;
        out_q[i]   = q;
        out_zh[i]  = __fadd_rn(xi, __fsub_rn(q, xi));
        out_idx[i] = (float)b;
    }
}

extern "C" void kernel_launch(void* const* d_in, const int* in_sizes, int n_in,
                              void* d_out, int out_size) {
    const float* x      = (const float*)d_in[0];
    const float* values = (const float*)d_in[1];
    float* out = (float*)d_out;
    int n = in_sizes[0];

    int n4 = (n + 3) / 4;
    int threads = 512;
    int per_block = threads * 2;
    int blocks = (n4 + per_block - 1) / per_block;
    gql_kernel<<<blocks, threads>>>(x, values, out, n);
}